// round 2
// baseline (speedup 1.0000x reference)
#include <cuda_runtime.h>

#define NPTS 12288
#define DIM 256
#define DQK 64
#define BM 64
#define BN 64
#define NTILES (NPTS / BN)

// Scratch for projected Q, K, V (device globals: no allocation allowed)
__device__ float g_Q[NPTS * DQK];   // 3 MB
__device__ float g_K[NPTS * DQK];   // 3 MB
__device__ float g_V[NPTS * DIM];   // 12 MB

// ============================================================================
// Kernel 1: normalize features + coords, compute Q/K/V projections.
// One block per 64 rows. x row = [feat_n(256), coords_n(3)] kept in smem.
// ============================================================================
extern "C" __global__ void __launch_bounds__(256)
proj_kernel(const float* __restrict__ feat,
            const int*   __restrict__ coords,
            const float* __restrict__ tstride,
            const float* __restrict__ Wq, const float* __restrict__ bq,
            const float* __restrict__ Wk, const float* __restrict__ bk,
            const float* __restrict__ Wv, const float* __restrict__ bv)
{
    extern __shared__ float xs[];           // [64][260] (stride 260, 4-aligned)
    const int XS = 260;
    const int t = threadIdx.x;
    const int rbase = blockIdx.x * BM;

    // ---- load features tile [64][256] into smem ----
    {
        const float4* src = (const float4*)(feat + (size_t)rbase * DIM);
        #pragma unroll
        for (int i = 0; i < 16; i++) {
            int idx = t + i * 256;          // float4 index in 64x64-float4 tile
            float4 v = src[idx];
            int row = idx >> 6;
            int col = (idx & 63) << 2;
            *(float4*)&xs[row * XS + col] = v;
        }
    }
    __syncthreads();

    // ---- L2 normalize each row: 4 threads per row ----
    {
        int r = t >> 2, q = t & 3;
        float ss = 0.f;
        #pragma unroll
        for (int i = 0; i < 16; i++) {
            float4 v = *(const float4*)&xs[r * XS + q * 64 + i * 4];
            ss += v.x * v.x + v.y * v.y + v.z * v.z + v.w * v.w;
        }
        ss += __shfl_xor_sync(0xffffffffu, ss, 1);
        ss += __shfl_xor_sync(0xffffffffu, ss, 2);
        float rn = 1.f / (sqrtf(ss) + 1e-6f);
        #pragma unroll
        for (int i = 0; i < 16; i++) {
            float4 v = *(float4*)&xs[r * XS + q * 64 + i * 4];
            v.x *= rn; v.y *= rn; v.z *= rn; v.w *= rn;
            *(float4*)&xs[r * XS + q * 64 + i * 4] = v;
        }
    }

    // ---- coords / stride, clamped ----
    if (t < 192) {
        int rr = t / 3, ci = t % 3;
        float tsv = fmaxf(tstride[ci], 1e-6f);
        float c = (float)coords[(size_t)(rbase + rr) * 3 + ci] / tsv;
        xs[rr * XS + 256 + ci] = fminf(fmaxf(c, -100.f), 100.f);
    }
    __syncthreads();

    // ---- V = x @ Wv + bv : one output column per thread, 64 rows ----
    {
        float acc[64];
        #pragma unroll
        for (int r = 0; r < 64; r++) acc[r] = 0.f;
        for (int i = 0; i < DIM + 3; i++) {
            float w = Wv[i * DIM + t];
            #pragma unroll
            for (int r = 0; r < 64; r++) acc[r] += xs[r * XS + i] * w;
        }
        float b = bv[t];
        #pragma unroll
        for (int r = 0; r < 64; r++)
            g_V[(size_t)(rbase + r) * DIM + t] = acc[r] + b;
    }

    // ---- Q = x @ Wq + bq : 4 thread-groups of 64 cols, 16 rows each ----
    {
        int j = t & 63, grp = t >> 6;
        float acc[16];
        #pragma unroll
        for (int r = 0; r < 16; r++) acc[r] = 0.f;
        for (int i = 0; i < DIM + 3; i++) {
            float w = Wq[i * DQK + j];
            #pragma unroll
            for (int r = 0; r < 16; r++) acc[r] += xs[(grp * 16 + r) * XS + i] * w;
        }
        float b = bq[j];
        #pragma unroll
        for (int r = 0; r < 16; r++)
            g_Q[(size_t)(rbase + grp * 16 + r) * DQK + j] = acc[r] + b;
    }

    // ---- K = x @ Wk + bk ----
    {
        int j = t & 63, grp = t >> 6;
        float acc[16];
        #pragma unroll
        for (int r = 0; r < 16; r++) acc[r] = 0.f;
        for (int i = 0; i < DIM + 3; i++) {
            float w = Wk[i * DQK + j];
            #pragma unroll
            for (int r = 0; r < 16; r++) acc[r] += xs[(grp * 16 + r) * XS + i] * w;
        }
        float b = bk[j];
        #pragma unroll
        for (int r = 0; r < 16; r++)
            g_K[(size_t)(rbase + grp * 16 + r) * DQK + j] = acc[r] + b;
    }
}

// ============================================================================
// Kernel 2: fused flash attention, fp32.
// Block = 64 query rows, 256 threads.
// Thread t: rg = t/16 -> query rows 4rg..4rg+3
//           cg = t%16 -> QK cols {cg, cg+16, cg+32, cg+48}; PV out cols [16cg,16cg+16)
// smem: Qs[64][64], KsT[64][65], Ss[64][64], Vs[64][64] float4  = 112.25 KB
// ============================================================================
extern "C" __global__ void __launch_bounds__(256, 2)
attn_kernel(const float* __restrict__ feat, float* __restrict__ out)
{
    extern __shared__ float smem[];
    float*  Qs  = smem;                         // 64*64
    float*  KsT = Qs + BM * DQK;                // 64*65 (transposed K, padded)
    float*  Ss  = KsT + DQK * (BN + 1);         // 64*64
    float4* Vs  = (float4*)(Ss + BM * BN);      // 64*64 float4 (=64x256 floats)

    const int t  = threadIdx.x;
    const int rg = t >> 4;
    const int cg = t & 15;
    const int r0 = rg << 2;
    const int qbase = blockIdx.x * BM;

    // load Q tile (straight copy, coalesced)
    {
        const float4* src = (const float4*)(g_Q + (size_t)qbase * DQK);
        float4* dst = (float4*)Qs;
        #pragma unroll
        for (int i = 0; i < 4; i++) dst[t + i * 256] = src[t + i * 256];
    }

    float m[4], l[4], acc[64];
    #pragma unroll
    for (int r = 0; r < 4; r++) { m[r] = -1e30f; l[r] = 0.f; }
    #pragma unroll
    for (int i = 0; i < 64; i++) acc[i] = 0.f;

    for (int kt = 0; kt < NTILES; kt++) {
        __syncthreads();   // previous PV done before overwriting K/V tiles

        // ---- load K tile transposed, V tile straight ----
        {
            const float4* ksrc = (const float4*)(g_K + (size_t)kt * BN * DQK);
            #pragma unroll
            for (int i = 0; i < 4; i++) {
                int idx = t + i * 256;          // float4 idx: row=idx/16, col4=idx%16
                float4 v = ksrc[idx];
                int row = idx >> 4;
                int col = (idx & 15) << 2;
                KsT[(col + 0) * (BN + 1) + row] = v.x;
                KsT[(col + 1) * (BN + 1) + row] = v.y;
                KsT[(col + 2) * (BN + 1) + row] = v.z;
                KsT[(col + 3) * (BN + 1) + row] = v.w;
            }
            const float4* vsrc = (const float4*)(g_V + (size_t)kt * BN * DIM);
            float4* vdst = (float4*)Vs;
            #pragma unroll
            for (int i = 0; i < 16; i++) vdst[t + i * 256] = vsrc[t + i * 256];
        }
        __syncthreads();

        // ---- QK^T for my 4 rows x 4 cols ----
        float sv[4][4];
        #pragma unroll
        for (int a = 0; a < 4; a++)
            #pragma unroll
            for (int b = 0; b < 4; b++) sv[a][b] = 0.f;

        #pragma unroll 16
        for (int d = 0; d < DQK; d++) {
            float k0 = KsT[d * (BN + 1) + cg];
            float k1 = KsT[d * (BN + 1) + cg + 16];
            float k2 = KsT[d * (BN + 1) + cg + 32];
            float k3 = KsT[d * (BN + 1) + cg + 48];
            float q0 = Qs[(r0 + 0) * DQK + d];
            float q1 = Qs[(r0 + 1) * DQK + d];
            float q2 = Qs[(r0 + 2) * DQK + d];
            float q3 = Qs[(r0 + 3) * DQK + d];
            sv[0][0] += q0 * k0; sv[0][1] += q0 * k1; sv[0][2] += q0 * k2; sv[0][3] += q0 * k3;
            sv[1][0] += q1 * k0; sv[1][1] += q1 * k1; sv[1][2] += q1 * k2; sv[1][3] += q1 * k3;
            sv[2][0] += q2 * k0; sv[2][1] += q2 * k1; sv[2][2] += q2 * k2; sv[2][3] += q2 * k3;
            sv[3][0] += q3 * k0; sv[3][1] += q3 * k1; sv[3][2] += q3 * k2; sv[3][3] += q3 * k3;
        }

        // ---- scale + clip + online softmax (per row, reduce over 16 lanes) ----
        #pragma unroll
        for (int r = 0; r < 4; r++) {
            float mx = -1e30f;
            #pragma unroll
            for (int j = 0; j < 4; j++) {
                float s = sv[r][j] * 0.125f;
                s = fminf(fmaxf(s, -100.f), 100.f);
                sv[r][j] = s;
                mx = fmaxf(mx, s);
            }
            #pragma unroll
            for (int o = 1; o < 16; o <<= 1)
                mx = fmaxf(mx, __shfl_xor_sync(0xffffffffu, mx, o));
            float mnew = fmaxf(m[r], mx);
            float corr = __expf(m[r] - mnew);
            float sum = 0.f;
            #pragma unroll
            for (int j = 0; j < 4; j++) {
                float e = __expf(sv[r][j] - mnew);
                sv[r][j] = e;
                sum += e;
            }
            #pragma unroll
            for (int o = 1; o < 16; o <<= 1)
                sum += __shfl_xor_sync(0xffffffffu, sum, o);
            l[r] = l[r] * corr + sum;
            m[r] = mnew;
            #pragma unroll
            for (int c = 0; c < 16; c++) acc[r * 16 + c] *= corr;
            #pragma unroll
            for (int j = 0; j < 4; j++)
                Ss[(r0 + r) * BN + cg + 16 * j] = sv[r][j];
        }
        __syncthreads();

        // ---- P @ V : each V float4 feeds 16 FFMAs ----
        #pragma unroll 4
        for (int kj = 0; kj < BN; kj++) {
            float p0 = Ss[(r0 + 0) * BN + kj];
            float p1 = Ss[(r0 + 1) * BN + kj];
            float p2 = Ss[(r0 + 2) * BN + kj];
            float p3 = Ss[(r0 + 3) * BN + kj];
            const float4* vrow = Vs + kj * (DIM / 4);
            #pragma unroll
            for (int cc = 0; cc < 4; cc++) {
                float4 v = vrow[cg * 4 + cc];
                acc[ 0 + cc * 4 + 0] += p0 * v.x; acc[ 0 + cc * 4 + 1] += p0 * v.y;
                acc[ 0 + cc * 4 + 2] += p0 * v.z; acc[ 0 + cc * 4 + 3] += p0 * v.w;
                acc[16 + cc * 4 + 0] += p1 * v.x; acc[16 + cc * 4 + 1] += p1 * v.y;
                acc[16 + cc * 4 + 2] += p1 * v.z; acc[16 + cc * 4 + 3] += p1 * v.w;
                acc[32 + cc * 4 + 0] += p2 * v.x; acc[32 + cc * 4 + 1] += p2 * v.y;
                acc[32 + cc * 4 + 2] += p2 * v.z; acc[32 + cc * 4 + 3] += p2 * v.w;
                acc[48 + cc * 4 + 0] += p3 * v.x; acc[48 + cc * 4 + 1] += p3 * v.y;
                acc[48 + cc * 4 + 2] += p3 * v.z; acc[48 + cc * 4 + 3] += p3 * v.w;
            }
        }
    }

    // ---- epilogue: divide by (l + 1e-6), add residual, store ----
    const float4* f4 = (const float4*)feat;
    float4* o4 = (float4*)out;
    #pragma unroll
    for (int r = 0; r < 4; r++) {
        size_t row = (size_t)(qbase + r0 + r);
        float inv = 1.f / (l[r] + 1e-6f);
        #pragma unroll
        for (int cc = 0; cc < 4; cc++) {
            float4 f = f4[row * (DIM / 4) + cg * 4 + cc];
            float4 o;
            o.x = acc[r * 16 + cc * 4 + 0] * inv + f.x;
            o.y = acc[r * 16 + cc * 4 + 1] * inv + f.y;
            o.z = acc[r * 16 + cc * 4 + 2] * inv + f.z;
            o.w = acc[r * 16 + cc * 4 + 3] * inv + f.w;
            o4[row * (DIM / 4) + cg * 4 + cc] = o;
        }
    }
}

// ============================================================================
// Launch
// ============================================================================
extern "C" void kernel_launch(void* const* d_in, const int* in_sizes, int n_in,
                              void* d_out, int out_size)
{
    (void)in_sizes; (void)n_in; (void)out_size;
    const float* feat   = (const float*)d_in[0];
    const int*   coords = (const int*)  d_in[1];
    const float* ts     = (const float*)d_in[2];
    const float* Wq     = (const float*)d_in[3];
    const float* bq     = (const float*)d_in[4];
    const float* Wk     = (const float*)d_in[5];
    const float* bk     = (const float*)d_in[6];
    const float* Wv     = (const float*)d_in[7];
    const float* bv     = (const float*)d_in[8];
    float* out = (float*)d_out;

    const int smem_proj = 64 * 260 * 4;                                     // 66560 B
    const int smem_attn = (BM*DQK + DQK*(BN+1) + BM*BN) * 4 + BN * 64 * 16; // 114944 B
    cudaFuncSetAttribute(proj_kernel, cudaFuncAttributeMaxDynamicSharedMemorySize, smem_proj);
    cudaFuncSetAttribute(attn_kernel, cudaFuncAttributeMaxDynamicSharedMemorySize, smem_attn);

    proj_kernel<<<NPTS / BM, 256, smem_proj>>>(feat, coords, ts, Wq, bq, Wk, bk, Wv, bv);
    attn_kernel<<<NPTS / BM, 256, smem_attn>>>(feat, out);
}

// round 7
// speedup vs baseline: 3.4555x; 3.4555x over previous
#include <cuda_runtime.h>
#include <cuda_bf16.h>
#include <cstdint>

#define NPTS 12288
#define DIM 256
#define DQK 64
#define BM 64
#define BN 64
#define NT (NPTS / BN)      // 192 kv tiles
#define NQB (NPTS / BM)     // 192 query blocks
#define THREADS 256

// ---------------- global scratch (bf16 split planes) ----------------
__device__ __align__(256) __nv_bfloat16 g_Qh[NPTS * DQK], g_Qm[NPTS * DQK], g_Ql[NPTS * DQK];
__device__ __align__(256) __nv_bfloat16 g_Kh[NPTS * DQK], g_Km[NPTS * DQK], g_Kl[NPTS * DQK];
__device__ __align__(256) __nv_bfloat16 g_Vth[DIM * NPTS], g_Vtl[DIM * NPTS];  // [feat][point]

extern __shared__ char dynsmem[];

// ---------------- small asm helpers (all base-sm_100 legal) ----------------
__device__ __forceinline__ uint32_t smem_u32(const void* p) {
    uint32_t a;
    asm("{ .reg .u64 t; cvta.to.shared.u64 t, %1; cvt.u32.u64 %0, t; }" : "=r"(a) : "l"(p));
    return a;
}
__device__ __forceinline__ void ldsm4(uint32_t* r, uint32_t addr) {
    asm volatile("ldmatrix.sync.aligned.m8n8.x4.shared.b16 {%0,%1,%2,%3}, [%4];"
                 : "=r"(r[0]), "=r"(r[1]), "=r"(r[2]), "=r"(r[3]) : "r"(addr));
}
__device__ __forceinline__ void mma16816(float* d, const uint32_t* a, const uint32_t* b) {
    asm volatile("mma.sync.aligned.m16n8k16.row.col.f32.bf16.bf16.f32 "
                 "{%0,%1,%2,%3}, {%4,%5,%6,%7}, {%8,%9}, {%0,%1,%2,%3};"
                 : "+f"(d[0]), "+f"(d[1]), "+f"(d[2]), "+f"(d[3])
                 : "r"(a[0]), "r"(a[1]), "r"(a[2]), "r"(a[3]), "r"(b[0]), "r"(b[1]));
}
#define CP16(dst_u32, src_ptr) \
    asm volatile("cp.async.cg.shared.global [%0], [%1], 16;" \
                 :: "r"(dst_u32), "l"(src_ptr) : "memory")
#define CP_COMMIT asm volatile("cp.async.commit_group;" ::: "memory")
#define CP_WAIT1  asm volatile("cp.async.wait_group 1;" ::: "memory")
#define CP_WAIT0  asm volatile("cp.async.wait_group 0;" ::: "memory")

// swizzled offset inside a row-major [rows][128B] tile (16B granules)
__device__ __forceinline__ uint32_t swz(uint32_t row, uint32_t c16) {
    return row * 128u + ((c16 * 16u) ^ ((row & 7u) * 16u));
}
// fast exp for x <= 0 (poly exp2, no MUFU). rel err ~6e-8.
__device__ __forceinline__ float eexp(float x) {
    float t = fmaxf(x * 1.4426950408889634f, -126.0f);
    float z = t + 12582912.0f;                    // round-to-nearest int in mantissa
    int   ii = __float_as_int(z) - __float_as_int(12582912.0f);
    float fr = t - (z - 12582912.0f);             // [-0.5, 0.5]
    float p = 9.61812911e-3f;
    p = fmaf(p, fr, 5.55041087e-2f);
    p = fmaf(p, fr, 2.40226507e-1f);
    p = fmaf(p, fr, 6.93147181e-1f);
    p = fmaf(p, fr, 1.0f);
    return __int_as_float(__float_as_int(p) + (ii << 23));
}
__device__ __forceinline__ uint32_t packbf(float a, float b) {
    __nv_bfloat162 v;
    v.x = __float2bfloat16(a);
    v.y = __float2bfloat16(b);
    return *reinterpret_cast<uint32_t*>(&v);
}

// ============================================================================
// Kernel 1: normalize + project; emit bf16 split planes.
// Q planes carry q*0.125 (scale folded; power of 2 so split is exact).
// ============================================================================
extern "C" __global__ void __launch_bounds__(256)
proj_kernel(const float* __restrict__ feat,
            const int*   __restrict__ coords,
            const float* __restrict__ tstride,
            const float* __restrict__ Wq, const float* __restrict__ bq,
            const float* __restrict__ Wk, const float* __restrict__ bk,
            const float* __restrict__ Wv, const float* __restrict__ bv)
{
    float* xs = (float*)dynsmem;            // [64][260]
    const int XS = 260;
    const int t = threadIdx.x;
    const int rbase = blockIdx.x * 64;

    {   // load feature tile [64][256]
        const float4* src = (const float4*)(feat + (size_t)rbase * DIM);
        #pragma unroll
        for (int i = 0; i < 16; i++) {
            int idx = t + i * 256;
            float4 v = src[idx];
            int row = idx >> 6, col = (idx & 63) << 2;
            *(float4*)&xs[row * XS + col] = v;
        }
    }
    __syncthreads();
    {   // L2 normalize (4 threads / row)
        int r = t >> 2, q = t & 3;
        float ss = 0.f;
        #pragma unroll
        for (int i = 0; i < 16; i++) {
            float4 v = *(const float4*)&xs[r * XS + q * 64 + i * 4];
            ss += v.x * v.x + v.y * v.y + v.z * v.z + v.w * v.w;
        }
        ss += __shfl_xor_sync(0xffffffffu, ss, 1);
        ss += __shfl_xor_sync(0xffffffffu, ss, 2);
        float rn = 1.f / (sqrtf(ss) + 1e-6f);
        #pragma unroll
        for (int i = 0; i < 16; i++) {
            float4 v = *(float4*)&xs[r * XS + q * 64 + i * 4];
            v.x *= rn; v.y *= rn; v.z *= rn; v.w *= rn;
            *(float4*)&xs[r * XS + q * 64 + i * 4] = v;
        }
    }
    if (t < 192) {
        int rr = t / 3, ci = t % 3;
        float tsv = fmaxf(tstride[ci], 1e-6f);
        float c = (float)coords[(size_t)(rbase + rr) * 3 + ci] / tsv;
        xs[rr * XS + 256 + ci] = fminf(fmaxf(c, -100.f), 100.f);
    }
    __syncthreads();

    // ---- V = x @ Wv + bv -> transposed 2-way bf16 split ----
    {
        float acc[64];
        #pragma unroll
        for (int r = 0; r < 64; r++) acc[r] = 0.f;
        for (int i = 0; i < DIM + 3; i++) {
            float w = Wv[i * DIM + t];
            #pragma unroll
            for (int r = 0; r < 64; r++) acc[r] += xs[r * XS + i] * w;
        }
        float b = bv[t];
        #pragma unroll
        for (int r = 0; r < 64; r += 2) {
            float v0 = acc[r] + b, v1 = acc[r + 1] + b;
            __nv_bfloat16 h0 = __float2bfloat16(v0), h1 = __float2bfloat16(v1);
            __nv_bfloat16 l0 = __float2bfloat16(v0 - __bfloat162float(h0));
            __nv_bfloat16 l1 = __float2bfloat16(v1 - __bfloat162float(h1));
            __nv_bfloat162 hh; hh.x = h0; hh.y = h1;
            __nv_bfloat162 ll; ll.x = l0; ll.y = l1;
            size_t idx = ((size_t)t * NPTS + rbase + r) >> 1;
            ((__nv_bfloat162*)g_Vth)[idx] = hh;
            ((__nv_bfloat162*)g_Vtl)[idx] = ll;
        }
    }
    // ---- Q = (x @ Wq + bq) * 0.125 -> 3-way split ----
    {
        int j = t & 63, grp = t >> 6;
        float acc[16];
        #pragma unroll
        for (int r = 0; r < 16; r++) acc[r] = 0.f;
        for (int i = 0; i < DIM + 3; i++) {
            float w = Wq[i * DQK + j];
            #pragma unroll
            for (int r = 0; r < 16; r++) acc[r] += xs[(grp * 16 + r) * XS + i] * w;
        }
        float b = bq[j];
        #pragma unroll
        for (int r = 0; r < 16; r++) {
            float q = (acc[r] + b) * 0.125f;
            __nv_bfloat16 h = __float2bfloat16(q);
            float rem = q - __bfloat162float(h);
            __nv_bfloat16 m = __float2bfloat16(rem);
            __nv_bfloat16 l = __float2bfloat16(rem - __bfloat162float(m));
            size_t idx = (size_t)(rbase + grp * 16 + r) * DQK + j;
            g_Qh[idx] = h; g_Qm[idx] = m; g_Ql[idx] = l;
        }
    }
    // ---- K = x @ Wk + bk -> 3-way split ----
    {
        int j = t & 63, grp = t >> 6;
        float acc[16];
        #pragma unroll
        for (int r = 0; r < 16; r++) acc[r] = 0.f;
        for (int i = 0; i < DIM + 3; i++) {
            float w = Wk[i * DQK + j];
            #pragma unroll
            for (int r = 0; r < 16; r++) acc[r] += xs[(grp * 16 + r) * XS + i] * w;
        }
        float b = bk[j];
        #pragma unroll
        for (int r = 0; r < 16; r++) {
            float k = acc[r] + b;
            __nv_bfloat16 h = __float2bfloat16(k);
            float rem = k - __bfloat162float(h);
            __nv_bfloat16 m = __float2bfloat16(rem);
            __nv_bfloat16 l = __float2bfloat16(rem - __bfloat162float(m));
            size_t idx = (size_t)(rbase + grp * 16 + r) * DQK + j;
            g_Kh[idx] = h; g_Km[idx] = m; g_Kl[idx] = l;
        }
    }
}

// ============================================================================
// Kernel 2: mma.sync flash attention.
// 192 CTAs x 64 rows. 8 warps = 4 row-groups x 2 col-halves.
// Each warp: 16 rows, full S (redundant in pair), 128 O cols.
// ============================================================================
#define SM_Q   0                       // 3 planes x 8192
#define SM_KV  24576
#define KVBUF  90112                   // Kh 0 / Km 8192 / Kl 16384 / Vh 24576 / Vl 57344
#define SMEM_ATTN (SM_KV + 2 * KVBUF)  // 204800

__device__ __forceinline__ void load_tile(uint32_t kvb, int kt, int t)
{
    // K planes: 64 rows x 128B each
    #pragma unroll
    for (int c = t; c < 512; c += THREADS) {
        uint32_t row = c >> 3, c16 = c & 7;
        const char* s0 = (const char*)(g_Kh + ((size_t)(kt * BN + row) * DQK + c16 * 8));
        const char* s1 = (const char*)(g_Km + ((size_t)(kt * BN + row) * DQK + c16 * 8));
        const char* s2 = (const char*)(g_Kl + ((size_t)(kt * BN + row) * DQK + c16 * 8));
        uint32_t d = swz(row, c16);
        CP16(kvb + d, s0);
        CP16(kvb + 8192 + d, s1);
        CP16(kvb + 16384 + d, s2);
    }
    // V^T planes: 256 feat rows x 128B (64 keys)
    #pragma unroll
    for (int c = t; c < 2048; c += THREADS) {
        uint32_t row = c >> 3, c16 = c & 7;
        const char* s0 = (const char*)(g_Vth + ((size_t)row * NPTS + kt * BN + c16 * 8));
        const char* s1 = (const char*)(g_Vtl + ((size_t)row * NPTS + kt * BN + c16 * 8));
        uint32_t d = swz(row, c16);
        CP16(kvb + 24576 + d, s0);
        CP16(kvb + 57344 + d, s1);
    }
}

extern "C" __global__ void __launch_bounds__(THREADS, 1)
attn_kernel(const float* __restrict__ feat, float* __restrict__ out)
{
    char* sm = dynsmem;
    const uint32_t sb = smem_u32(sm);
    const int t = threadIdx.x;
    const int lane = t & 31;
    const int w = t >> 5;
    const int rg = w & 3;          // row group (16 rows)
    const int ch = w >> 2;         // col half (128 cols)
    const int qbase = blockIdx.x * BM;

    // ---- stage Q planes into smem (swizzled) ----
    #pragma unroll
    for (int c = t; c < 512; c += THREADS) {
        uint32_t row = c >> 3, c16 = c & 7;
        size_t e = (size_t)(qbase + row) * DQK + c16 * 8;
        uint32_t d = swz(row, c16);
        *(uint4*)(sm + SM_Q + d)         = *(const uint4*)(g_Qh + e);
        *(uint4*)(sm + SM_Q + 8192 + d)  = *(const uint4*)(g_Qm + e);
        *(uint4*)(sm + SM_Q + 16384 + d) = *(const uint4*)(g_Ql + e);
    }
    // prefetch tile 0
    load_tile(sb + SM_KV, 0, t);
    CP_COMMIT;
    __syncthreads();

    // ---- Q A-fragments (held in registers for entire kernel) ----
    uint32_t qh[16], qm[16], ql[16];
    {
        int m = lane >> 3, r = lane & 7;
        uint32_t row = rg * 16 + ((m & 1) << 3) + r;
        #pragma unroll
        for (int kt = 0; kt < 4; kt++) {
            uint32_t c16 = kt * 2 + (m >> 1);
            uint32_t off = swz(row, c16);
            ldsm4(&qh[kt * 4], sb + SM_Q + off);
            ldsm4(&qm[kt * 4], sb + SM_Q + 8192 + off);
            ldsm4(&ql[kt * 4], sb + SM_Q + 16384 + off);
        }
    }

    float o[16][4];
    #pragma unroll
    for (int i = 0; i < 16; i++)
        #pragma unroll
        for (int j = 0; j < 4; j++) o[i][j] = 0.f;
    float mA = -100.f, mB = -100.f, lA = 0.f, lB = 0.f;

    int buf = 0;
    for (int kt = 0; kt < NT; kt++) {
        const uint32_t kvb = sb + SM_KV + buf * KVBUF;
        if (kt + 1 < NT) {
            load_tile(sb + SM_KV + (buf ^ 1) * KVBUF, kt + 1, t);
            CP_COMMIT;
            CP_WAIT1;
        } else {
            CP_WAIT0;
        }
        __syncthreads();

        // ================= QK^T (6-way split, fp32 accum) =================
        float s[8][4];
        #pragma unroll
        for (int i = 0; i < 8; i++)
            #pragma unroll
            for (int j = 0; j < 4; j++) s[i][j] = 0.f;

        {
            int m = lane >> 3, r = lane & 7;
            #pragma unroll
            for (int nt = 0; nt < 8; nt++) {
                uint32_t row = nt * 8 + r;
                uint32_t kh[8], km[8], kl[8];
                #pragma unroll
                for (int P = 0; P < 2; P++) {
                    uint32_t off = swz(row, P * 4 + m);
                    ldsm4(&kh[P * 4], kvb + off);
                    ldsm4(&km[P * 4], kvb + 8192 + off);
                    ldsm4(&kl[P * 4], kvb + 16384 + off);
                }
                #pragma unroll
                for (int k2 = 0; k2 < 4; k2++) {
                    mma16816(s[nt], &qh[k2 * 4], &kh[k2 * 2]);
                    mma16816(s[nt], &qh[k2 * 4], &km[k2 * 2]);
                    mma16816(s[nt], &qm[k2 * 4], &kh[k2 * 2]);
                    mma16816(s[nt], &qm[k2 * 4], &km[k2 * 2]);
                    mma16816(s[nt], &qh[k2 * 4], &kl[k2 * 2]);
                    mma16816(s[nt], &ql[k2 * 4], &kh[k2 * 2]);
                }
            }
        }

        // ================= online softmax (per warp, no smem) ============
        float mxA = -1e30f, mxB = -1e30f;
        #pragma unroll
        for (int nt = 0; nt < 8; nt++) {
            #pragma unroll
            for (int j = 0; j < 4; j++) {
                float v = fminf(fmaxf(s[nt][j], -100.f), 100.f);
                s[nt][j] = v;
                if (j < 2) mxA = fmaxf(mxA, v); else mxB = fmaxf(mxB, v);
            }
        }
        mxA = fmaxf(mxA, __shfl_xor_sync(0xffffffffu, mxA, 1));
        mxA = fmaxf(mxA, __shfl_xor_sync(0xffffffffu, mxA, 2));
        mxB = fmaxf(mxB, __shfl_xor_sync(0xffffffffu, mxB, 1));
        mxB = fmaxf(mxB, __shfl_xor_sync(0xffffffffu, mxB, 2));
        float mnA = fmaxf(mA, mxA), mnB = fmaxf(mB, mxB);
        float cA = eexp(mA - mnA), cB = eexp(mB - mnB);
        mA = mnA; mB = mnB;
        #pragma unroll
        for (int i = 0; i < 16; i++) {
            o[i][0] *= cA; o[i][1] *= cA; o[i][2] *= cB; o[i][3] *= cB;
        }

        uint32_t ph[16], pl[16];
        float tsA = 0.f, tsB = 0.f;
        #pragma unroll
        for (int nt = 0; nt < 8; nt++) {
            float p0 = eexp(s[nt][0] - mA);
            float p1 = eexp(s[nt][1] - mA);
            float p2 = eexp(s[nt][2] - mB);
            float p3 = eexp(s[nt][3] - mB);
            tsA += p0 + p1; tsB += p2 + p3;
            float h0 = __bfloat162float(__float2bfloat16(p0));
            float h1 = __bfloat162float(__float2bfloat16(p1));
            float h2 = __bfloat162float(__float2bfloat16(p2));
            float h3 = __bfloat162float(__float2bfloat16(p3));
            int base = 4 * (nt >> 1) + (nt & 1) * 2;
            ph[base]     = packbf(h0, h1);
            ph[base + 1] = packbf(h2, h3);
            pl[base]     = packbf(p0 - h0, p1 - h1);
            pl[base + 1] = packbf(p2 - h2, p3 - h3);
        }
        tsA += __shfl_xor_sync(0xffffffffu, tsA, 1);
        tsA += __shfl_xor_sync(0xffffffffu, tsA, 2);
        tsB += __shfl_xor_sync(0xffffffffu, tsB, 1);
        tsB += __shfl_xor_sync(0xffffffffu, tsB, 2);
        lA = lA * cA + tsA;
        lB = lB * cB + tsB;

        // ================= P @ V (3-way split) ===========================
        {
            int m = lane >> 3, r = lane & 7;
            #pragma unroll
            for (int nt2 = 0; nt2 < 16; nt2++) {
                uint32_t row = ch * 128 + nt2 * 8 + r;
                uint32_t vh[8], vl[8];
                #pragma unroll
                for (int P = 0; P < 2; P++) {
                    uint32_t off = swz(row, P * 4 + m);
                    ldsm4(&vh[P * 4], kvb + 24576 + off);
                    ldsm4(&vl[P * 4], kvb + 57344 + off);
                }
                #pragma unroll
                for (int k2 = 0; k2 < 4; k2++) {
                    mma16816(o[nt2], &ph[k2 * 4], &vh[k2 * 2]);
                    mma16816(o[nt2], &pl[k2 * 4], &vh[k2 * 2]);
                    mma16816(o[nt2], &ph[k2 * 4], &vl[k2 * 2]);
                }
            }
        }
        __syncthreads();   // everyone done with this buffer before it is refilled
        buf ^= 1;
    }

    // ================= epilogue: /(l+1e-6) + residual =================
    {
        float invA = 1.f / (lA + 1e-6f);
        float invB = 1.f / (lB + 1e-6f);
        int rA = qbase + rg * 16 + (lane >> 2);
        int rB = rA + 8;
        #pragma unroll
        for (int nt2 = 0; nt2 < 16; nt2++) {
            int c = ch * 128 + nt2 * 8 + (lane & 3) * 2;
            float2 fa = *(const float2*)(feat + (size_t)rA * DIM + c);
            float2 fb = *(const float2*)(feat + (size_t)rB * DIM + c);
            float2 oa, ob;
            oa.x = o[nt2][0] * invA + fa.x;
            oa.y = o[nt2][1] * invA + fa.y;
            ob.x = o[nt2][2] * invB + fb.x;
            ob.y = o[nt2][3] * invB + fb.y;
            *(float2*)(out + (size_t)rA * DIM + c) = oa;
            *(float2*)(out + (size_t)rB * DIM + c) = ob;
        }
    }
}

// ============================================================================
extern "C" void kernel_launch(void* const* d_in, const int* in_sizes, int n_in,
                              void* d_out, int out_size)
{
    (void)in_sizes; (void)n_in; (void)out_size;
    const float* feat   = (const float*)d_in[0];
    const int*   coords = (const int*)  d_in[1];
    const float* ts     = (const float*)d_in[2];
    const float* Wq     = (const float*)d_in[3];
    const float* bq     = (const float*)d_in[4];
    const float* Wk     = (const float*)d_in[5];
    const float* bk     = (const float*)d_in[6];
    const float* Wv     = (const float*)d_in[7];
    const float* bv     = (const float*)d_in[8];
    float* out = (float*)d_out;

    const int smem_proj = 64 * 260 * 4;
    cudaFuncSetAttribute(proj_kernel, cudaFuncAttributeMaxDynamicSharedMemorySize, smem_proj);
    cudaFuncSetAttribute(attn_kernel, cudaFuncAttributeMaxDynamicSharedMemorySize, SMEM_ATTN);

    proj_kernel<<<NPTS / 64, 256, smem_proj>>>(feat, coords, ts, Wq, bq, Wk, bk, Wv, bv);
    attn_kernel<<<NQB, THREADS, SMEM_ATTN>>>(feat, out);
}

// round 8
// speedup vs baseline: 5.3412x; 1.5457x over previous
#include <cuda_runtime.h>
#include <cuda_bf16.h>
#include <cstdint>

#define NPTS 12288
#define DIM 256
#define DQK 64
#define BM 64
#define BN 64
#define NT (NPTS / BN)      // 192 kv tiles total
#define NQB (NPTS / BM)     // 192 query blocks
#define NSPLIT 2
#define NTH (NT / NSPLIT)   // 96 kv tiles per split unit
#define THREADS 256

// ---------------- global scratch ----------------
__device__ __align__(256) __nv_bfloat16 g_Qh[NPTS * DQK], g_Qm[NPTS * DQK], g_Ql[NPTS * DQK];
__device__ __align__(256) __nv_bfloat16 g_Kh[NPTS * DQK], g_Km[NPTS * DQK], g_Kl[NPTS * DQK];
__device__ __align__(256) __nv_bfloat16 g_Vth[DIM * NPTS], g_Vtl[DIM * NPTS];  // [feat][point]
// KV-split partials (unnormalized O, per-row m and l)
__device__ __align__(256) float g_Op[NSPLIT * NPTS * DIM];
__device__ float g_mx[NSPLIT * NPTS];
__device__ float g_ls[NSPLIT * NPTS];

extern __shared__ char dynsmem[];

// ---------------- asm helpers (base sm_100 legal) ----------------
__device__ __forceinline__ uint32_t smem_u32(const void* p) {
    uint32_t a;
    asm("{ .reg .u64 t; cvta.to.shared.u64 t, %1; cvt.u32.u64 %0, t; }" : "=r"(a) : "l"(p));
    return a;
}
__device__ __forceinline__ void ldsm4(uint32_t* r, uint32_t addr) {
    asm volatile("ldmatrix.sync.aligned.m8n8.x4.shared.b16 {%0,%1,%2,%3}, [%4];"
                 : "=r"(r[0]), "=r"(r[1]), "=r"(r[2]), "=r"(r[3]) : "r"(addr));
}
__device__ __forceinline__ void mma16816(float* d, const uint32_t* a, const uint32_t* b) {
    asm volatile("mma.sync.aligned.m16n8k16.row.col.f32.bf16.bf16.f32 "
                 "{%0,%1,%2,%3}, {%4,%5,%6,%7}, {%8,%9}, {%0,%1,%2,%3};"
                 : "+f"(d[0]), "+f"(d[1]), "+f"(d[2]), "+f"(d[3])
                 : "r"(a[0]), "r"(a[1]), "r"(a[2]), "r"(a[3]), "r"(b[0]), "r"(b[1]));
}
#define CP16(dst_u32, src_ptr) \
    asm volatile("cp.async.cg.shared.global [%0], [%1], 16;" \
                 :: "r"(dst_u32), "l"(src_ptr) : "memory")
#define CP_COMMIT asm volatile("cp.async.commit_group;" ::: "memory")
#define CP_WAIT1  asm volatile("cp.async.wait_group 1;" ::: "memory")
#define CP_WAIT0  asm volatile("cp.async.wait_group 0;" ::: "memory")

__device__ __forceinline__ uint32_t swz(uint32_t row, uint32_t c16) {
    return row * 128u + (((c16 ^ (row & 7u)) & 7u) * 16u) + ((c16 >> 3) * 128u * 0u) + ((c16 & 8u) ? 0u : 0u);
}
// NOTE: rows here are always 128B wide (8 granules), c16 in [0,8)
// fast exp for x <= 0 (poly exp2, no MUFU). rel err ~6e-8.
__device__ __forceinline__ float eexp(float x) {
    float t = fmaxf(x * 1.4426950408889634f, -126.0f);
    float z = t + 12582912.0f;
    int   ii = __float_as_int(z) - __float_as_int(12582912.0f);
    float fr = t - (z - 12582912.0f);
    float p = 9.61812911e-3f;
    p = fmaf(p, fr, 5.55041087e-2f);
    p = fmaf(p, fr, 2.40226507e-1f);
    p = fmaf(p, fr, 6.93147181e-1f);
    p = fmaf(p, fr, 1.0f);
    return __int_as_float(__float_as_int(p) + (ii << 23));
}
__device__ __forceinline__ uint32_t packbf(float a, float b) {
    __nv_bfloat162 v;
    v.x = __float2bfloat16(a);
    v.y = __float2bfloat16(b);
    return *reinterpret_cast<uint32_t*>(&v);
}

// ============================================================================
// Kernel 1: normalize + project; bf16 split planes (Q scaled by 0.125).
// ============================================================================
extern "C" __global__ void __launch_bounds__(256)
proj_kernel(const float* __restrict__ feat,
            const int*   __restrict__ coords,
            const float* __restrict__ tstride,
            const float* __restrict__ Wq, const float* __restrict__ bq,
            const float* __restrict__ Wk, const float* __restrict__ bk,
            const float* __restrict__ Wv, const float* __restrict__ bv)
{
    float* xs = (float*)dynsmem;            // [64][260]
    const int XS = 260;
    const int t = threadIdx.x;
    const int rbase = blockIdx.x * 64;

    {
        const float4* src = (const float4*)(feat + (size_t)rbase * DIM);
        #pragma unroll
        for (int i = 0; i < 16; i++) {
            int idx = t + i * 256;
            float4 v = src[idx];
            int row = idx >> 6, col = (idx & 63) << 2;
            *(float4*)&xs[row * XS + col] = v;
        }
    }
    __syncthreads();
    {
        int r = t >> 2, q = t & 3;
        float ss = 0.f;
        #pragma unroll
        for (int i = 0; i < 16; i++) {
            float4 v = *(const float4*)&xs[r * XS + q * 64 + i * 4];
            ss += v.x * v.x + v.y * v.y + v.z * v.z + v.w * v.w;
        }
        ss += __shfl_xor_sync(0xffffffffu, ss, 1);
        ss += __shfl_xor_sync(0xffffffffu, ss, 2);
        float rn = 1.f / (sqrtf(ss) + 1e-6f);
        #pragma unroll
        for (int i = 0; i < 16; i++) {
            float4 v = *(float4*)&xs[r * XS + q * 64 + i * 4];
            v.x *= rn; v.y *= rn; v.z *= rn; v.w *= rn;
            *(float4*)&xs[r * XS + q * 64 + i * 4] = v;
        }
    }
    if (t < 192) {
        int rr = t / 3, ci = t % 3;
        float tsv = fmaxf(tstride[ci], 1e-6f);
        float c = (float)coords[(size_t)(rbase + rr) * 3 + ci] / tsv;
        xs[rr * XS + 256 + ci] = fminf(fmaxf(c, -100.f), 100.f);
    }
    __syncthreads();

    {   // V -> transposed 2-way split
        float acc[64];
        #pragma unroll
        for (int r = 0; r < 64; r++) acc[r] = 0.f;
        for (int i = 0; i < DIM + 3; i++) {
            float w = Wv[i * DIM + t];
            #pragma unroll
            for (int r = 0; r < 64; r++) acc[r] += xs[r * XS + i] * w;
        }
        float b = bv[t];
        #pragma unroll
        for (int r = 0; r < 64; r += 2) {
            float v0 = acc[r] + b, v1 = acc[r + 1] + b;
            __nv_bfloat16 h0 = __float2bfloat16(v0), h1 = __float2bfloat16(v1);
            __nv_bfloat16 l0 = __float2bfloat16(v0 - __bfloat162float(h0));
            __nv_bfloat16 l1 = __float2bfloat16(v1 - __bfloat162float(h1));
            __nv_bfloat162 hh; hh.x = h0; hh.y = h1;
            __nv_bfloat162 ll; ll.x = l0; ll.y = l1;
            size_t idx = ((size_t)t * NPTS + rbase + r) >> 1;
            ((__nv_bfloat162*)g_Vth)[idx] = hh;
            ((__nv_bfloat162*)g_Vtl)[idx] = ll;
        }
    }
    {   // Q * 0.125 -> 3-way split
        int j = t & 63, grp = t >> 6;
        float acc[16];
        #pragma unroll
        for (int r = 0; r < 16; r++) acc[r] = 0.f;
        for (int i = 0; i < DIM + 3; i++) {
            float w = Wq[i * DQK + j];
            #pragma unroll
            for (int r = 0; r < 16; r++) acc[r] += xs[(grp * 16 + r) * XS + i] * w;
        }
        float b = bq[j];
        #pragma unroll
        for (int r = 0; r < 16; r++) {
            float q = (acc[r] + b) * 0.125f;
            __nv_bfloat16 h = __float2bfloat16(q);
            float rem = q - __bfloat162float(h);
            __nv_bfloat16 m = __float2bfloat16(rem);
            __nv_bfloat16 l = __float2bfloat16(rem - __bfloat162float(m));
            size_t idx = (size_t)(rbase + grp * 16 + r) * DQK + j;
            g_Qh[idx] = h; g_Qm[idx] = m; g_Ql[idx] = l;
        }
    }
    {   // K -> 3-way split
        int j = t & 63, grp = t >> 6;
        float acc[16];
        #pragma unroll
        for (int r = 0; r < 16; r++) acc[r] = 0.f;
        for (int i = 0; i < DIM + 3; i++) {
            float w = Wk[i * DQK + j];
            #pragma unroll
            for (int r = 0; r < 16; r++) acc[r] += xs[(grp * 16 + r) * XS + i] * w;
        }
        float b = bk[j];
        #pragma unroll
        for (int r = 0; r < 16; r++) {
            float k = acc[r] + b;
            __nv_bfloat16 h = __float2bfloat16(k);
            float rem = k - __bfloat162float(h);
            __nv_bfloat16 m = __float2bfloat16(rem);
            __nv_bfloat16 l = __float2bfloat16(rem - __bfloat162float(m));
            size_t idx = (size_t)(rbase + grp * 16 + r) * DQK + j;
            g_Kh[idx] = h; g_Km[idx] = m; g_Kl[idx] = l;
        }
    }
}

// ============================================================================
// Kernel 2: mma.sync flash attention, S-col split across warp pairs,
// KV-split 2 (grid 384), partial (O, m, l) output.
// ============================================================================
#define SM_Q   0                        // 3 planes x 8192 = 24576
#define SM_P   24576                    // ph 8192 (4 rg x 16 x 128B) + pl 8192
#define SM_RED 40960                    // pmax[8][16] f + psum[8][16] f = 1024
#define SM_KV  41984
#define KVBUF  90112                    // Kh 0 / Km 8192 / Kl 16384 / Vh 24576 / Vl 57344
#define SMEM_ATTN (SM_KV + 2 * KVBUF)   // 222208

__device__ __forceinline__ void load_tile(uint32_t kvb, int kt, int t)
{
    #pragma unroll
    for (int c = t; c < 512; c += THREADS) {
        uint32_t row = c >> 3, c16 = c & 7;
        const char* s0 = (const char*)(g_Kh + ((size_t)(kt * BN + row) * DQK + c16 * 8));
        const char* s1 = (const char*)(g_Km + ((size_t)(kt * BN + row) * DQK + c16 * 8));
        const char* s2 = (const char*)(g_Kl + ((size_t)(kt * BN + row) * DQK + c16 * 8));
        uint32_t d = swz(row, c16);
        CP16(kvb + d, s0);
        CP16(kvb + 8192 + d, s1);
        CP16(kvb + 16384 + d, s2);
    }
    #pragma unroll
    for (int c = t; c < 2048; c += THREADS) {
        uint32_t row = c >> 3, c16 = c & 7;
        const char* s0 = (const char*)(g_Vth + ((size_t)row * NPTS + kt * BN + c16 * 8));
        const char* s1 = (const char*)(g_Vtl + ((size_t)row * NPTS + kt * BN + c16 * 8));
        uint32_t d = swz(row, c16);
        CP16(kvb + 24576 + d, s0);
        CP16(kvb + 57344 + d, s1);
    }
}

extern "C" __global__ void __launch_bounds__(THREADS, 1)
attn_kernel()
{
    char* sm = dynsmem;
    const uint32_t sb = smem_u32(sm);
    const int t = threadIdx.x;
    const int lane = t & 31;
    const int w = t >> 5;
    const int rg = w & 3;           // row group (16 rows)
    const int ch = w >> 2;          // col half: S keys [ch*32, ch*32+32)
    const int qb = blockIdx.x >> 1;
    const int half = blockIdx.x & 1;
    const int kt0 = half * NTH;
    const int qbase = qb * BM;

    // ---- stage Q planes ----
    #pragma unroll
    for (int c = t; c < 512; c += THREADS) {
        uint32_t row = c >> 3, c16 = c & 7;
        size_t e = (size_t)(qbase + row) * DQK + c16 * 8;
        uint32_t d = swz(row, c16);
        *(uint4*)(sm + SM_Q + d)         = *(const uint4*)(g_Qh + e);
        *(uint4*)(sm + SM_Q + 8192 + d)  = *(const uint4*)(g_Qm + e);
        *(uint4*)(sm + SM_Q + 16384 + d) = *(const uint4*)(g_Ql + e);
    }
    load_tile(sb + SM_KV, kt0, t);
    CP_COMMIT;
    __syncthreads();

    // ---- Q A-fragments resident in registers ----
    uint32_t qh[16], qm[16], ql[16];
    const int fm = lane >> 3, fr = lane & 7;
    {
        uint32_t row = rg * 16 + ((fm & 1) << 3) + fr;
        #pragma unroll
        for (int k2 = 0; k2 < 4; k2++) {
            uint32_t off = swz(row, k2 * 2 + (fm >> 1));
            ldsm4(&qh[k2 * 4], sb + SM_Q + off);
            ldsm4(&qm[k2 * 4], sb + SM_Q + 8192 + off);
            ldsm4(&ql[k2 * 4], sb + SM_Q + 16384 + off);
        }
    }

    float o[16][4];
    #pragma unroll
    for (int i = 0; i < 16; i++)
        #pragma unroll
        for (int j = 0; j < 4; j++) o[i][j] = 0.f;
    float mA = -100.f, mB = -100.f, lA = 0.f, lB = 0.f;

    float* pmax = (float*)(sm + SM_RED);         // [8 warps][16 rows]
    float* psum = (float*)(sm + SM_RED + 512);
    const uint32_t phbase = sb + SM_P + rg * 2048;
    const uint32_t plbase = phbase + 8192;

    int buf = 0;
    for (int i = 0; i < NTH; i++) {
        const uint32_t kvb = sb + SM_KV + buf * KVBUF;
        if (i + 1 < NTH) {
            load_tile(sb + SM_KV + (buf ^ 1) * KVBUF, kt0 + i + 1, t);
            CP_COMMIT;
            CP_WAIT1;
        } else {
            CP_WAIT0;
        }
        __syncthreads();

        // ========== QK^T: this warp computes keys [ch*32, ch*32+32) ==========
        float s[4][4], s2[4][4];
        #pragma unroll
        for (int a = 0; a < 4; a++)
            #pragma unroll
            for (int b = 0; b < 4; b++) { s[a][b] = 0.f; s2[a][b] = 0.f; }

        #pragma unroll
        for (int nt = 0; nt < 4; nt++) {
            uint32_t row = (ch * 4 + nt) * 8 + fr;     // key index
            uint32_t kh[8], km[8], kl[8];
            #pragma unroll
            for (int P = 0; P < 2; P++) {
                uint32_t off = swz(row, P * 4 + fm);
                ldsm4(&kh[P * 4], kvb + off);
                ldsm4(&km[P * 4], kvb + 8192 + off);
                ldsm4(&kl[P * 4], kvb + 16384 + off);
            }
            #pragma unroll
            for (int k2 = 0; k2 < 4; k2++) {
                mma16816(s[nt],  &qh[k2 * 4], &kh[k2 * 2]);
                mma16816(s[nt],  &qh[k2 * 4], &km[k2 * 2]);
                mma16816(s[nt],  &qm[k2 * 4], &kh[k2 * 2]);
                mma16816(s2[nt], &qm[k2 * 4], &km[k2 * 2]);
                mma16816(s2[nt], &qh[k2 * 4], &kl[k2 * 2]);
                mma16816(s2[nt], &ql[k2 * 4], &kh[k2 * 2]);
            }
        }

        // ========== softmax: cross-warp max exchange ==========
        float mxA = -1e30f, mxB = -1e30f;
        #pragma unroll
        for (int nt = 0; nt < 4; nt++) {
            #pragma unroll
            for (int j = 0; j < 4; j++) {
                float v = fminf(fmaxf(s[nt][j] + s2[nt][j], -100.f), 100.f);
                s[nt][j] = v;
                if (j < 2) mxA = fmaxf(mxA, v); else mxB = fmaxf(mxB, v);
            }
        }
        mxA = fmaxf(mxA, __shfl_xor_sync(0xffffffffu, mxA, 1));
        mxA = fmaxf(mxA, __shfl_xor_sync(0xffffffffu, mxA, 2));
        mxB = fmaxf(mxB, __shfl_xor_sync(0xffffffffu, mxB, 1));
        mxB = fmaxf(mxB, __shfl_xor_sync(0xffffffffu, mxB, 2));
        if ((lane & 3) == 0) {
            pmax[(rg * 2 + ch) * 16 + (lane >> 2)]     = mxA;
            pmax[(rg * 2 + ch) * 16 + 8 + (lane >> 2)] = mxB;
        }
        __syncthreads();
        mxA = fmaxf(mxA, pmax[(rg * 2 + (ch ^ 1)) * 16 + (lane >> 2)]);
        mxB = fmaxf(mxB, pmax[(rg * 2 + (ch ^ 1)) * 16 + 8 + (lane >> 2)]);
        float mnA = fmaxf(mA, mxA), mnB = fmaxf(mB, mxB);
        float cA = eexp(mA - mnA), cB = eexp(mB - mnB);
        mA = mnA; mB = mnB;
        #pragma unroll
        for (int i2 = 0; i2 < 16; i2++) {
            o[i2][0] *= cA; o[i2][1] *= cA; o[i2][2] *= cB; o[i2][3] *= cB;
        }

        // ========== exp, write P halves to smem, partial sums ==========
        float tsA = 0.f, tsB = 0.f;
        {
            uint32_t rA = lane >> 2, rB = rA + 8;
            uint32_t colb = 4u * (lane & 3);
            #pragma unroll
            for (int nt = 0; nt < 4; nt++) {
                uint32_t g = ch * 4 + nt;
                float p0 = eexp(s[nt][0] - mA);
                float p1 = eexp(s[nt][1] - mA);
                float p2 = eexp(s[nt][2] - mB);
                float p3 = eexp(s[nt][3] - mB);
                tsA += p0 + p1; tsB += p2 + p3;
                float h0 = __bfloat162float(__float2bfloat16(p0));
                float h1 = __bfloat162float(__float2bfloat16(p1));
                float h2 = __bfloat162float(__float2bfloat16(p2));
                float h3 = __bfloat162float(__float2bfloat16(p3));
                uint32_t offA = rA * 128u + (((g ^ (rA & 7u)) & 7u) << 4) + colb;
                uint32_t offB = rB * 128u + (((g ^ (rB & 7u)) & 7u) << 4) + colb;
                *(uint32_t*)(sm + (phbase - sb) + offA) = packbf(h0, h1);
                *(uint32_t*)(sm + (plbase - sb) + offA) = packbf(p0 - h0, p1 - h1);
                *(uint32_t*)(sm + (phbase - sb) + offB) = packbf(h2, h3);
                *(uint32_t*)(sm + (plbase - sb) + offB) = packbf(p2 - h2, p3 - h3);
            }
        }
        tsA += __shfl_xor_sync(0xffffffffu, tsA, 1);
        tsA += __shfl_xor_sync(0xffffffffu, tsA, 2);
        tsB += __shfl_xor_sync(0xffffffffu, tsB, 1);
        tsB += __shfl_xor_sync(0xffffffffu, tsB, 2);
        if ((lane & 3) == 0) {
            psum[(rg * 2 + ch) * 16 + (lane >> 2)]     = tsA;
            psum[(rg * 2 + ch) * 16 + 8 + (lane >> 2)] = tsB;
        }
        __syncthreads();
        lA = lA * cA + tsA + psum[(rg * 2 + (ch ^ 1)) * 16 + (lane >> 2)];
        lB = lB * cB + tsB + psum[(rg * 2 + (ch ^ 1)) * 16 + 8 + (lane >> 2)];

        // ========== load full-width P A-frags from smem ==========
        uint32_t ph[16], pl[16];
        {
            uint32_t row = ((fm & 1) << 3) + fr;
            #pragma unroll
            for (int k2 = 0; k2 < 4; k2++) {
                uint32_t off = swz(row, k2 * 2 + (fm >> 1));
                ldsm4(&ph[k2 * 4], phbase + off);
                ldsm4(&pl[k2 * 4], plbase + off);
            }
        }

        // ========== P @ V ==========
        #pragma unroll
        for (int nt2 = 0; nt2 < 16; nt2++) {
            uint32_t row = ch * 128 + nt2 * 8 + fr;    // feature index
            uint32_t vh[8], vl[8];
            #pragma unroll
            for (int P = 0; P < 2; P++) {
                uint32_t off = swz(row, P * 4 + fm);
                ldsm4(&vh[P * 4], kvb + 24576 + off);
                ldsm4(&vl[P * 4], kvb + 57344 + off);
            }
            #pragma unroll
            for (int k2 = 0; k2 < 4; k2++) {
                mma16816(o[nt2], &ph[k2 * 4], &vh[k2 * 2]);
                mma16816(o[nt2], &pl[k2 * 4], &vh[k2 * 2]);
                mma16816(o[nt2], &ph[k2 * 4], &vl[k2 * 2]);
            }
        }
        __syncthreads();
        buf ^= 1;
    }

    // ========== partial epilogue: unnormalized O + (m, l) ==========
    {
        int rA = qbase + rg * 16 + (lane >> 2);
        int rB = rA + 8;
        float* Ob = g_Op + (size_t)half * NPTS * DIM;
        #pragma unroll
        for (int nt2 = 0; nt2 < 16; nt2++) {
            int c = ch * 128 + nt2 * 8 + (lane & 3) * 2;
            float2 oa, ob;
            oa.x = o[nt2][0]; oa.y = o[nt2][1];
            ob.x = o[nt2][2]; ob.y = o[nt2][3];
            *(float2*)(Ob + (size_t)rA * DIM + c) = oa;
            *(float2*)(Ob + (size_t)rB * DIM + c) = ob;
        }
        if (ch == 0 && (lane & 3) == 0) {
            g_mx[half * NPTS + rA] = mA;
            g_ls[half * NPTS + rA] = lA;
            g_mx[half * NPTS + rB] = mB;
            g_ls[half * NPTS + rB] = lB;
        }
    }
}

// ============================================================================
// Kernel 3: combine KV-split partials, divide, add residual.
// ============================================================================
extern "C" __global__ void __launch_bounds__(256)
reduce_kernel(const float* __restrict__ feat, float* __restrict__ out)
{
    int row = blockIdx.x;
    int c = threadIdx.x;
    float m0 = g_mx[row], m1 = g_mx[NPTS + row];
    float l0 = g_ls[row], l1 = g_ls[NPTS + row];
    float M = fmaxf(m0, m1);
    float w0 = eexp(m0 - M), w1 = eexp(m1 - M);
    float den = 1.f / (l0 * w0 + l1 * w1 + 1e-6f);
    float v0 = g_Op[(size_t)row * DIM + c];
    float v1 = g_Op[(size_t)(NPTS + row) * DIM + c];
    out[(size_t)row * DIM + c] = (v0 * w0 + v1 * w1) * den + feat[(size_t)row * DIM + c];
}

// ============================================================================
extern "C" void kernel_launch(void* const* d_in, const int* in_sizes, int n_in,
                              void* d_out, int out_size)
{
    (void)in_sizes; (void)n_in; (void)out_size;
    const float* feat   = (const float*)d_in[0];
    const int*   coords = (const int*)  d_in[1];
    const float* ts     = (const float*)d_in[2];
    const float* Wq     = (const float*)d_in[3];
    const float* bq     = (const float*)d_in[4];
    const float* Wk     = (const float*)d_in[5];
    const float* bk     = (const float*)d_in[6];
    const float* Wv     = (const float*)d_in[7];
    const float* bv     = (const float*)d_in[8];
    float* out = (float*)d_out;

    const int smem_proj = 64 * 260 * 4;
    cudaFuncSetAttribute(proj_kernel, cudaFuncAttributeMaxDynamicSharedMemorySize, smem_proj);
    cudaFuncSetAttribute(attn_kernel, cudaFuncAttributeMaxDynamicSharedMemorySize, SMEM_ATTN);

    proj_kernel<<<NPTS / 64, 256, smem_proj>>>(feat, coords, ts, Wq, bq, Wk, bk, Wv, bv);
    attn_kernel<<<NQB * NSPLIT, THREADS, SMEM_ATTN>>>();
    reduce_kernel<<<NPTS, 256>>>(feat, out);
}

// round 9
// speedup vs baseline: 6.7944x; 1.2721x over previous
#include <cuda_runtime.h>
#include <cuda_bf16.h>
#include <cstdint>

#define NPTS 12288
#define DIM 256
#define DQK 64
#define BM 64
#define BN 64
#define NQB (NPTS / BM)     // 192 query blocks
#define NSPLIT 3
#define NTH (NPTS / BN / NSPLIT)   // 64 kv tiles per split unit
#define THREADS 256

// ---------------- global scratch ----------------
__device__ __align__(256) __nv_bfloat16 g_Qh[NPTS * DQK], g_Qm[NPTS * DQK];
__device__ __align__(256) __nv_bfloat16 g_Kh[NPTS * DQK], g_Km[NPTS * DQK];
__device__ __align__(256) __nv_bfloat16 g_Vth[DIM * NPTS], g_Vtl[DIM * NPTS];  // [feat][point]
__device__ __align__(256) float g_Op[NSPLIT * NPTS * DIM];
__device__ float g_mx[NSPLIT * NPTS];
__device__ float g_ls[NSPLIT * NPTS];

extern __shared__ char dynsmem[];

// ---------------- asm helpers (base sm_100 legal) ----------------
__device__ __forceinline__ uint32_t smem_u32(const void* p) {
    uint32_t a;
    asm("{ .reg .u64 t; cvta.to.shared.u64 t, %1; cvt.u32.u64 %0, t; }" : "=r"(a) : "l"(p));
    return a;
}
__device__ __forceinline__ void ldsm4(uint32_t* r, uint32_t addr) {
    asm volatile("ldmatrix.sync.aligned.m8n8.x4.shared.b16 {%0,%1,%2,%3}, [%4];"
                 : "=r"(r[0]), "=r"(r[1]), "=r"(r[2]), "=r"(r[3]) : "r"(addr));
}
__device__ __forceinline__ void mma16816(float* d, const uint32_t* a, const uint32_t* b) {
    asm volatile("mma.sync.aligned.m16n8k16.row.col.f32.bf16.bf16.f32 "
                 "{%0,%1,%2,%3}, {%4,%5,%6,%7}, {%8,%9}, {%0,%1,%2,%3};"
                 : "+f"(d[0]), "+f"(d[1]), "+f"(d[2]), "+f"(d[3])
                 : "r"(a[0]), "r"(a[1]), "r"(a[2]), "r"(a[3]), "r"(b[0]), "r"(b[1]));
}
#define CP16(dst_u32, src_ptr) \
    asm volatile("cp.async.cg.shared.global [%0], [%1], 16;" \
                 :: "r"(dst_u32), "l"(src_ptr) : "memory")
#define CP_COMMIT asm volatile("cp.async.commit_group;" ::: "memory")
#define CP_WAIT1  asm volatile("cp.async.wait_group 1;" ::: "memory")
#define CP_WAIT0  asm volatile("cp.async.wait_group 0;" ::: "memory")

__device__ __forceinline__ uint32_t swz(uint32_t row, uint32_t c16) {
    return row * 128u + (((c16 ^ row) & 7u) * 16u);
}
// fast exp for x <= 0 (poly exp2, no MUFU). rel err ~6e-8.
__device__ __forceinline__ float eexp(float x) {
    float t = fmaxf(x * 1.4426950408889634f, -126.0f);
    float z = t + 12582912.0f;
    int   ii = __float_as_int(z) - __float_as_int(12582912.0f);
    float fr = t - (z - 12582912.0f);
    float p = 9.61812911e-3f;
    p = fmaf(p, fr, 5.55041087e-2f);
    p = fmaf(p, fr, 2.40226507e-1f);
    p = fmaf(p, fr, 6.93147181e-1f);
    p = fmaf(p, fr, 1.0f);
    return __int_as_float(__float_as_int(p) + (ii << 23));
}
__device__ __forceinline__ uint32_t packbf(float a, float b) {
    __nv_bfloat162 v;
    v.x = __float2bfloat16(a);
    v.y = __float2bfloat16(b);
    return *reinterpret_cast<uint32_t*>(&v);
}

// ============================================================================
// Kernel 1: normalize + project. Register-tiled GEMM: thread = 8 rows x 12 cols
// over combined output [V(256) | Q(64) | K(64)]. W streamed from L2.
// ============================================================================
extern "C" __global__ void __launch_bounds__(256)
proj_kernel(const float* __restrict__ feat,
            const int*   __restrict__ coords,
            const float* __restrict__ tstride,
            const float* __restrict__ Wq, const float* __restrict__ bq,
            const float* __restrict__ Wk, const float* __restrict__ bk,
            const float* __restrict__ Wv, const float* __restrict__ bv)
{
    float* xs = (float*)dynsmem;            // [64][260]
    const int XS = 260;
    const int t = threadIdx.x;
    const int rbase = blockIdx.x * 64;

    {   // load feature tile [64][256]
        const float4* src = (const float4*)(feat + (size_t)rbase * DIM);
        #pragma unroll
        for (int i = 0; i < 16; i++) {
            int idx = t + i * 256;
            float4 v = src[idx];
            int row = idx >> 6, col = (idx & 63) << 2;
            *(float4*)&xs[row * XS + col] = v;
        }
    }
    __syncthreads();
    {   // L2 normalize (4 threads / row)
        int r = t >> 2, q = t & 3;
        float ss = 0.f;
        #pragma unroll
        for (int i = 0; i < 16; i++) {
            float4 v = *(const float4*)&xs[r * XS + q * 64 + i * 4];
            ss += v.x * v.x + v.y * v.y + v.z * v.z + v.w * v.w;
        }
        ss += __shfl_xor_sync(0xffffffffu, ss, 1);
        ss += __shfl_xor_sync(0xffffffffu, ss, 2);
        float rn = 1.f / (sqrtf(ss) + 1e-6f);
        #pragma unroll
        for (int i = 0; i < 16; i++) {
            float4 v = *(float4*)&xs[r * XS + q * 64 + i * 4];
            v.x *= rn; v.y *= rn; v.z *= rn; v.w *= rn;
            *(float4*)&xs[r * XS + q * 64 + i * 4] = v;
        }
    }
    if (t < 192) {
        int rr = t / 3, ci = t % 3;
        float tsv = fmaxf(tstride[ci], 1e-6f);
        float c = (float)coords[(size_t)(rbase + rr) * 3 + ci] / tsv;
        xs[rr * XS + 256 + ci] = fminf(fmaxf(c, -100.f), 100.f);
    }
    __syncthreads();

    // ---- register-tiled GEMM ----
    const int cg = t & 31;                // column group
    const int r0 = (t >> 5) * 8;          // 8 rows
    const bool isQ = cg < 16;
    const float* WC = isQ ? (Wq + cg * 4) : (Wk + (cg - 16) * 4);

    float acc[12][8];
    #pragma unroll
    for (int c = 0; c < 12; c++)
        #pragma unroll
        for (int r = 0; r < 8; r++) acc[c][r] = 0.f;

    #pragma unroll 2
    for (int i = 0; i < DIM + 3; i++) {
        float xv[8];
        #pragma unroll
        for (int r = 0; r < 8; r++) xv[r] = xs[(r0 + r) * XS + i];
        float4 wA = *(const float4*)(Wv + (size_t)i * 256 + cg * 4);
        float4 wB = *(const float4*)(Wv + (size_t)i * 256 + 128 + cg * 4);
        float4 wC = *(const float4*)(WC + (size_t)i * 64);
        #pragma unroll
        for (int r = 0; r < 8; r++) {
            acc[0][r] = fmaf(wA.x, xv[r], acc[0][r]);
            acc[1][r] = fmaf(wA.y, xv[r], acc[1][r]);
            acc[2][r] = fmaf(wA.z, xv[r], acc[2][r]);
            acc[3][r] = fmaf(wA.w, xv[r], acc[3][r]);
            acc[4][r] = fmaf(wB.x, xv[r], acc[4][r]);
            acc[5][r] = fmaf(wB.y, xv[r], acc[5][r]);
            acc[6][r] = fmaf(wB.z, xv[r], acc[6][r]);
            acc[7][r] = fmaf(wB.w, xv[r], acc[7][r]);
            acc[8][r]  = fmaf(wC.x, xv[r], acc[8][r]);
            acc[9][r]  = fmaf(wC.y, xv[r], acc[9][r]);
            acc[10][r] = fmaf(wC.z, xv[r], acc[10][r]);
            acc[11][r] = fmaf(wC.w, xv[r], acc[11][r]);
        }
    }

    // ---- epilogue: V (8 cols, transposed 2-way split) ----
    float4 bA = *(const float4*)(bv + cg * 4);
    float4 bB = *(const float4*)(bv + 128 + cg * 4);
    #pragma unroll
    for (int j = 0; j < 8; j++) {
        int col = (j < 4) ? (cg * 4 + j) : (128 + cg * 4 + (j - 4));
        float bb = (j < 4) ? ((float*)&bA)[j] : ((float*)&bB)[j - 4];
        uint32_t hp[4], lp[4];
        #pragma unroll
        for (int r2 = 0; r2 < 4; r2++) {
            float v0 = acc[j][2 * r2] + bb;
            float v1 = acc[j][2 * r2 + 1] + bb;
            float h0 = __bfloat162float(__float2bfloat16(v0));
            float h1 = __bfloat162float(__float2bfloat16(v1));
            hp[r2] = packbf(h0, h1);
            lp[r2] = packbf(v0 - h0, v1 - h1);
        }
        size_t base = (size_t)col * NPTS + rbase + r0;
        uint4 uh; uh.x = hp[0]; uh.y = hp[1]; uh.z = hp[2]; uh.w = hp[3];
        uint4 ul; ul.x = lp[0]; ul.y = lp[1]; ul.z = lp[2]; ul.w = lp[3];
        *(uint4*)(g_Vth + base) = uh;
        *(uint4*)(g_Vtl + base) = ul;
    }
    // ---- epilogue: Q or K (4 cols, 2-way split; Q scaled by 0.125) ----
    {
        const float* bC = isQ ? (bq + cg * 4) : (bk + (cg - 16) * 4);
        float4 bc4 = *(const float4*)bC;
        __nv_bfloat16* Gh = isQ ? g_Qh : g_Kh;
        __nv_bfloat16* Gm = isQ ? g_Qm : g_Km;
        int cqk = isQ ? cg * 4 : (cg - 16) * 4;
        float scale = isQ ? 0.125f : 1.f;
        #pragma unroll
        for (int j = 0; j < 4; j++) {
            float bb = ((float*)&bc4)[j];
            #pragma unroll
            for (int r = 0; r < 8; r++) {
                float v = (acc[8 + j][r] + bb) * scale;
                __nv_bfloat16 h = __float2bfloat16(v);
                __nv_bfloat16 m = __float2bfloat16(v - __bfloat162float(h));
                size_t idx = (size_t)(rbase + r0 + r) * DQK + cqk + j;
                Gh[idx] = h; Gm[idx] = m;
            }
        }
    }
}

// ============================================================================
// Kernel 2: mma.sync flash attention. S-cols split across warp pairs,
// P own-half kept in registers (C->A frag identity), partner half via smem.
// KV-split 3 (grid 576), partial (O, m, l) output.
// ============================================================================
#define SM_Q   0                        // Qh 8192 + Qm 8192
#define SM_P   16384                    // ph 8192 (4 rg x 16 x 128B) + pl 8192
#define SM_RED 32768                    // pmax[8][16] + psum[8][16] = 1024
#define SM_KV  33792
#define KVBUF  81920                    // Kh 0 / Km 8192 / Vh 16384 / Vl 49152
#define SMEM_ATTN (SM_KV + 2 * KVBUF)   // 197632

__device__ __forceinline__ void load_tile(uint32_t kvb, int kt, int t)
{
    #pragma unroll
    for (int c = t; c < 512; c += THREADS) {
        uint32_t row = c >> 3, c16 = c & 7;
        uint32_t d = swz(row, c16);
        CP16(kvb + d,        (const char*)(g_Kh + ((size_t)(kt * BN + row) * DQK + c16 * 8)));
        CP16(kvb + 8192 + d, (const char*)(g_Km + ((size_t)(kt * BN + row) * DQK + c16 * 8)));
    }
    #pragma unroll
    for (int c = t; c < 2048; c += THREADS) {
        uint32_t row = c >> 3, c16 = c & 7;
        uint32_t d = swz(row, c16);
        CP16(kvb + 16384 + d, (const char*)(g_Vth + ((size_t)row * NPTS + kt * BN + c16 * 8)));
        CP16(kvb + 49152 + d, (const char*)(g_Vtl + ((size_t)row * NPTS + kt * BN + c16 * 8)));
    }
}

extern "C" __global__ void __launch_bounds__(THREADS, 1)
attn_kernel()
{
    char* sm = dynsmem;
    const uint32_t sb = smem_u32(sm);
    const int t = threadIdx.x;
    const int lane = t & 31;
    const int w = t >> 5;
    const int rg = w & 3;           // row group (16 rows)
    const int ch = w >> 2;          // col half: S keys [ch*32, ch*32+32); O feats [ch*128,..)
    const int qb = blockIdx.x / NSPLIT;
    const int sp = blockIdx.x - qb * NSPLIT;
    const int kt0 = sp * NTH;
    const int qbase = qb * BM;

    // ---- stage Q planes ----
    #pragma unroll
    for (int c = t; c < 512; c += THREADS) {
        uint32_t row = c >> 3, c16 = c & 7;
        size_t e = (size_t)(qbase + row) * DQK + c16 * 8;
        uint32_t d = swz(row, c16);
        *(uint4*)(sm + SM_Q + d)        = *(const uint4*)(g_Qh + e);
        *(uint4*)(sm + SM_Q + 8192 + d) = *(const uint4*)(g_Qm + e);
    }
    load_tile(sb + SM_KV, kt0, t);
    CP_COMMIT;
    __syncthreads();

    // ---- Q A-fragments resident in registers ----
    uint32_t qh[16], qm[16];
    const int fm = lane >> 3, fr = lane & 7;
    {
        uint32_t row = rg * 16 + ((fm & 1) << 3) + fr;
        #pragma unroll
        for (int k2 = 0; k2 < 4; k2++) {
            uint32_t off = swz(row, k2 * 2 + (fm >> 1));
            ldsm4(&qh[k2 * 4], sb + SM_Q + off);
            ldsm4(&qm[k2 * 4], sb + SM_Q + 8192 + off);
        }
    }

    float o[16][4];
    #pragma unroll
    for (int i = 0; i < 16; i++)
        #pragma unroll
        for (int j = 0; j < 4; j++) o[i][j] = 0.f;
    float mA = -100.f, mB = -100.f, lA = 0.f, lB = 0.f;

    float* pmax = (float*)(sm + SM_RED);         // [8 warps][16 rows]
    float* psum = (float*)(sm + SM_RED + 512);
    const uint32_t phoff = SM_P + rg * 2048;     // this rg's P region (char offset)
    const uint32_t ploff = phoff + 8192;

    int buf = 0;
    for (int i = 0; i < NTH; i++) {
        const uint32_t kvb = sb + SM_KV + buf * KVBUF;
        if (i + 1 < NTH) {
            load_tile(sb + SM_KV + (buf ^ 1) * KVBUF, kt0 + i + 1, t);
            CP_COMMIT;
            CP_WAIT1;
        } else {
            CP_WAIT0;
        }
        __syncthreads();

        // ========== QK^T: 2-way x 2-way split (4 MMA combos) ==========
        float s[4][4], s2[4][4];
        #pragma unroll
        for (int a = 0; a < 4; a++)
            #pragma unroll
            for (int b = 0; b < 4; b++) { s[a][b] = 0.f; s2[a][b] = 0.f; }

        #pragma unroll
        for (int nt = 0; nt < 4; nt++) {
            uint32_t row = (ch * 4 + nt) * 8 + fr;     // key index
            uint32_t kh[8], km[8];
            #pragma unroll
            for (int P = 0; P < 2; P++) {
                uint32_t off = swz(row, P * 4 + fm);
                ldsm4(&kh[P * 4], kvb + off);
                ldsm4(&km[P * 4], kvb + 8192 + off);
            }
            #pragma unroll
            for (int k2 = 0; k2 < 4; k2++) {
                mma16816(s[nt],  &qh[k2 * 4], &kh[k2 * 2]);
                mma16816(s[nt],  &qh[k2 * 4], &km[k2 * 2]);
                mma16816(s2[nt], &qm[k2 * 4], &kh[k2 * 2]);
                mma16816(s2[nt], &qm[k2 * 4], &km[k2 * 2]);
            }
        }

        // ========== softmax: cross-warp max exchange ==========
        float mxA = -1e30f, mxB = -1e30f;
        #pragma unroll
        for (int nt = 0; nt < 4; nt++) {
            #pragma unroll
            for (int j = 0; j < 4; j++) {
                float v = fminf(fmaxf(s[nt][j] + s2[nt][j], -100.f), 100.f);
                s[nt][j] = v;
                if (j < 2) mxA = fmaxf(mxA, v); else mxB = fmaxf(mxB, v);
            }
        }
        mxA = fmaxf(mxA, __shfl_xor_sync(0xffffffffu, mxA, 1));
        mxA = fmaxf(mxA, __shfl_xor_sync(0xffffffffu, mxA, 2));
        mxB = fmaxf(mxB, __shfl_xor_sync(0xffffffffu, mxB, 1));
        mxB = fmaxf(mxB, __shfl_xor_sync(0xffffffffu, mxB, 2));
        if ((lane & 3) == 0) {
            pmax[(rg * 2 + ch) * 16 + (lane >> 2)]     = mxA;
            pmax[(rg * 2 + ch) * 16 + 8 + (lane >> 2)] = mxB;
        }
        __syncthreads();
        mxA = fmaxf(mxA, pmax[(rg * 2 + (ch ^ 1)) * 16 + (lane >> 2)]);
        mxB = fmaxf(mxB, pmax[(rg * 2 + (ch ^ 1)) * 16 + 8 + (lane >> 2)]);
        float mnA = fmaxf(mA, mxA), mnB = fmaxf(mB, mxB);
        float cA = eexp(mA - mnA), cB = eexp(mB - mnB);
        mA = mnA; mB = mnB;
        #pragma unroll
        for (int i2 = 0; i2 < 16; i2++) {
            o[i2][0] *= cA; o[i2][1] *= cA; o[i2][2] *= cB; o[i2][3] *= cB;
        }

        // ========== exp; own-half P kept as A-frags AND written to smem ======
        uint32_t phO[8], plO[8];
        float tsA = 0.f, tsB = 0.f;
        {
            uint32_t rA = lane >> 2, rB = rA + 8;
            uint32_t colb = 4u * (lane & 3);
            #pragma unroll
            for (int nt = 0; nt < 4; nt++) {
                uint32_t g = ch * 4 + nt;
                float p0 = eexp(s[nt][0] - mA);
                float p1 = eexp(s[nt][1] - mA);
                float p2 = eexp(s[nt][2] - mB);
                float p3 = eexp(s[nt][3] - mB);
                tsA += p0 + p1; tsB += p2 + p3;
                float h0 = __bfloat162float(__float2bfloat16(p0));
                float h1 = __bfloat162float(__float2bfloat16(p1));
                float h2 = __bfloat162float(__float2bfloat16(p2));
                float h3 = __bfloat162float(__float2bfloat16(p3));
                uint32_t pa = packbf(h0, h1), pb = packbf(h2, h3);
                uint32_t qa = packbf(p0 - h0, p1 - h1), qb = packbf(p2 - h2, p3 - h3);
                int bi = (nt >> 1) * 4 + (nt & 1) * 2;   // C->A frag identity
                phO[bi] = pa; phO[bi + 1] = pb;
                plO[bi] = qa; plO[bi + 1] = qb;
                uint32_t offA = rA * 128u + (((g ^ rA) & 7u) << 4) + colb;
                uint32_t offB = rB * 128u + (((g ^ rB) & 7u) << 4) + colb;
                *(uint32_t*)(sm + phoff + offA) = pa;
                *(uint32_t*)(sm + ploff + offA) = qa;
                *(uint32_t*)(sm + phoff + offB) = pb;
                *(uint32_t*)(sm + ploff + offB) = qb;
            }
        }
        tsA += __shfl_xor_sync(0xffffffffu, tsA, 1);
        tsA += __shfl_xor_sync(0xffffffffu, tsA, 2);
        tsB += __shfl_xor_sync(0xffffffffu, tsB, 1);
        tsB += __shfl_xor_sync(0xffffffffu, tsB, 2);
        if ((lane & 3) == 0) {
            psum[(rg * 2 + ch) * 16 + (lane >> 2)]     = tsA;
            psum[(rg * 2 + ch) * 16 + 8 + (lane >> 2)] = tsB;
        }

        // ========== PV, own key half (register P frags; overlaps exchange) ==
        #pragma unroll
        for (int nt2 = 0; nt2 < 16; nt2++) {
            uint32_t row = ch * 128 + nt2 * 8 + fr;    // feature index
            uint32_t vh[4], vl[4];
            uint32_t off = swz(row, ch * 4 + fm);
            ldsm4(vh, kvb + 16384 + off);
            ldsm4(vl, kvb + 49152 + off);
            #pragma unroll
            for (int c2 = 0; c2 < 2; c2++) {
                mma16816(o[nt2], &phO[c2 * 4], &vh[c2 * 2]);
                mma16816(o[nt2], &plO[c2 * 4], &vh[c2 * 2]);
                mma16816(o[nt2], &phO[c2 * 4], &vl[c2 * 2]);
            }
        }
        __syncthreads();   // partner P + psum visible
        lA = lA * cA + tsA + psum[(rg * 2 + (ch ^ 1)) * 16 + (lane >> 2)];
        lB = lB * cB + tsB + psum[(rg * 2 + (ch ^ 1)) * 16 + 8 + (lane >> 2)];

        // ========== partner P frags from smem ==========
        uint32_t phP[8], plP[8];
        {
            uint32_t row = ((fm & 1) << 3) + fr;
            #pragma unroll
            for (int c2 = 0; c2 < 2; c2++) {
                uint32_t c16 = ((1 ^ ch) * 2 + c2) * 2 + (fm >> 1);
                uint32_t off = swz(row, c16);
                ldsm4(&phP[c2 * 4], sb + phoff + off);
                ldsm4(&plP[c2 * 4], sb + ploff + off);
            }
        }

        // ========== PV, partner key half ==========
        #pragma unroll
        for (int nt2 = 0; nt2 < 16; nt2++) {
            uint32_t row = ch * 128 + nt2 * 8 + fr;
            uint32_t vh[4], vl[4];
            uint32_t off = swz(row, (1 ^ ch) * 4 + fm);
            ldsm4(vh, kvb + 16384 + off);
            ldsm4(vl, kvb + 49152 + off);
            #pragma unroll
            for (int c2 = 0; c2 < 2; c2++) {
                mma16816(o[nt2], &phP[c2 * 4], &vh[c2 * 2]);
                mma16816(o[nt2], &plP[c2 * 4], &vh[c2 * 2]);
                mma16816(o[nt2], &phP[c2 * 4], &vl[c2 * 2]);
            }
        }
        __syncthreads();   // done with this KV buffer + P region
        buf ^= 1;
    }

    // ========== partial epilogue: unnormalized O + (m, l) ==========
    {
        int rA = qbase + rg * 16 + (lane >> 2);
        int rB = rA + 8;
        float* Ob = g_Op + (size_t)sp * NPTS * DIM;
        #pragma unroll
        for (int nt2 = 0; nt2 < 16; nt2++) {
            int c = ch * 128 + nt2 * 8 + (lane & 3) * 2;
            float2 oa, ob;
            oa.x = o[nt2][0]; oa.y = o[nt2][1];
            ob.x = o[nt2][2]; ob.y = o[nt2][3];
            *(float2*)(Ob + (size_t)rA * DIM + c) = oa;
            *(float2*)(Ob + (size_t)rB * DIM + c) = ob;
        }
        if (ch == 0 && (lane & 3) == 0) {
            g_mx[sp * NPTS + rA] = mA;
            g_ls[sp * NPTS + rA] = lA;
            g_mx[sp * NPTS + rB] = mB;
            g_ls[sp * NPTS + rB] = lB;
        }
    }
}

// ============================================================================
// Kernel 3: combine KV-split partials, divide, add residual.
// ============================================================================
extern "C" __global__ void __launch_bounds__(256)
reduce_kernel(const float* __restrict__ feat, float* __restrict__ out)
{
    int row = blockIdx.x;
    int c = threadIdx.x;
    float m0 = g_mx[row], m1 = g_mx[NPTS + row], m2 = g_mx[2 * NPTS + row];
    float l0 = g_ls[row], l1 = g_ls[NPTS + row], l2 = g_ls[2 * NPTS + row];
    float M = fmaxf(m0, fmaxf(m1, m2));
    float w0 = eexp(m0 - M), w1 = eexp(m1 - M), w2 = eexp(m2 - M);
    float den = 1.f / (l0 * w0 + l1 * w1 + l2 * w2 + 1e-6f);
    float v0 = g_Op[(size_t)row * DIM + c];
    float v1 = g_Op[(size_t)(NPTS + row) * DIM + c];
    float v2 = g_Op[(size_t)(2 * NPTS + row) * DIM + c];
    out[(size_t)row * DIM + c] =
        (v0 * w0 + v1 * w1 + v2 * w2) * den + feat[(size_t)row * DIM + c];
}

// ============================================================================
extern "C" void kernel_launch(void* const* d_in, const int* in_sizes, int n_in,
                              void* d_out, int out_size)
{
    (void)in_sizes; (void)n_in; (void)out_size;
    const float* feat   = (const float*)d_in[0];
    const int*   coords = (const int*)  d_in[1];
    const float* ts     = (const float*)d_in[2];
    const float* Wq     = (const float*)d_in[3];
    const float* bq     = (const float*)d_in[4];
    const float* Wk     = (const float*)d_in[5];
    const float* bk     = (const float*)d_in[6];
    const float* Wv     = (const float*)d_in[7];
    const float* bv     = (const float*)d_in[8];
    float* out = (float*)d_out;

    const int smem_proj = 64 * 260 * 4;
    cudaFuncSetAttribute(proj_kernel, cudaFuncAttributeMaxDynamicSharedMemorySize, smem_proj);
    cudaFuncSetAttribute(attn_kernel, cudaFuncAttributeMaxDynamicSharedMemorySize, SMEM_ATTN);

    proj_kernel<<<NPTS / 64, 256, smem_proj>>>(feat, coords, ts, Wq, bq, Wk, bk, Wv, bv);
    attn_kernel<<<NQB * NSPLIT, THREADS, SMEM_ATTN>>>();
    reduce_kernel<<<NPTS, 256>>>(feat, out);
}